// round 12
// baseline (speedup 1.0000x reference)
#include <cuda_runtime.h>
#include <cstdint>

// ============================================================================
// simpleRQA: out[n] = any_m( cos_sim(Ex[n], Ey[m]) > 0.9 )
//
// K0: zero atomicMax cells + flag count.
// K1: normalize+quantize rows to int8; head(512)/tail/resid norms -> bounds.
// K2: int8 IMMA GEMM over HEAD 512 dims, A resident (64KB), NSPLIT=2 tn
//     tiles/CTA (grid 2048 -> 7 waves, ~1% tail). Conservative screen -> list.
// K3: full-K (1024) int8 dp4a rescreen of flagged rows, parallel over Ey.
// K4: exact fp32 check for doubly-flagged rows (statistically none).
// ============================================================================

#define NROWS   8192
#define DIMS    1024
#define BM_     128
#define BN_     128
#define NCHUNK  4                   // 4 chunks of 128 int8 = 512 head dims
#define NSPLIT  2                   // tn tiles per CTA
#define NQ      (NCHUNK * NSPLIT)   // 8 streamed B chunks per CTA
#define GT_     256                 // 8 warps: 4M x 2N

#define A_BYTES      (NCHUNK * BM_ * 128)     // 64 KB resident A
#define B_STAGE      (BN_ * 128)              // 16 KB per B stage
#define SMEM_DYN     (A_BYTES + 3 * B_STAGE + 1024)

static __device__ uint4 g_Xq[(size_t)NROWS * DIMS / 16];
static __device__ uint4 g_Yq[(size_t)NROWS * DIMS / 16];
static __device__ int   g_flag[NROWS];
static __device__ int   g_flag2[NROWS];
static __device__ int   g_list[NROWS];
static __device__ int   g_nflag;
// [0]=ExH [1]=Hx [2]=Tx [3]=EyH [4]=Hy [5]=Ty [6]=ExF [7]=EyF  (float bits)
static __device__ int   g_max8[8];

// ---------------------------------------------------------------------------
static __device__ __forceinline__ uint32_t smem_u32(const void* p) {
    uint32_t a;
    asm("{ .reg .u64 t; cvta.to.shared.u64 t, %1; cvt.u32.u64 %0, t; }"
        : "=r"(a) : "l"(p));
    return a;
}
static __device__ __forceinline__ void cp_async16(uint32_t dst, const void* src) {
    asm volatile("cp.async.cg.shared.global [%0], [%1], 16;"
                 :: "r"(dst), "l"(src) : "memory");
}
#define CP_COMMIT() asm volatile("cp.async.commit_group;" ::: "memory")
#define CP_WAIT(n)  asm volatile("cp.async.wait_group %0;" :: "n"(n) : "memory")

static __device__ __forceinline__ void ldmatrix_x4(
    uint32_t& r0, uint32_t& r1, uint32_t& r2, uint32_t& r3, uint32_t addr) {
    asm volatile("ldmatrix.sync.aligned.m8n8.x4.shared.b16 {%0,%1,%2,%3}, [%4];"
                 : "=r"(r0), "=r"(r1), "=r"(r2), "=r"(r3) : "r"(addr));
}
static __device__ __forceinline__ void mma_s8(
    int32_t* c, uint32_t a0, uint32_t a1, uint32_t a2, uint32_t a3,
    uint32_t b0, uint32_t b1) {
    asm volatile(
        "mma.sync.aligned.m16n8k32.row.col.s32.s8.s8.s32 "
        "{%0,%1,%2,%3}, {%4,%5,%6,%7}, {%8,%9}, {%0,%1,%2,%3};"
        : "+r"(c[0]), "+r"(c[1]), "+r"(c[2]), "+r"(c[3])
        : "r"(a0), "r"(a1), "r"(a2), "r"(a3), "r"(b0), "r"(b1));
}
static __device__ __forceinline__ uint32_t swz(uint32_t off) {
    return off ^ ((off >> 3) & 0x70);
}
static __device__ __forceinline__ float blk_sum(float v, float* ws, int tid) {
    #pragma unroll
    for (int o = 16; o > 0; o >>= 1) v += __shfl_xor_sync(0xFFFFFFFFu, v, o);
    if ((tid & 31) == 0) ws[tid >> 5] = v;
    __syncthreads();
    float t = ws[0] + ws[1] + ws[2] + ws[3] + ws[4] + ws[5] + ws[6] + ws[7];
    __syncthreads();
    return t;
}

// ---------------------------------------------------------------------------
__global__ void rqa_init()
{
    if (threadIdx.x < 8) g_max8[threadIdx.x] = 0;
    if (threadIdx.x == 8) g_nflag = 0;
}

// ---------------------------------------------------------------------------
// K1: normalize -> int8; head(512)/tail/resid norms -> maxima; zero out/flags.
// ---------------------------------------------------------------------------
__global__ void __launch_bounds__(256) rqa_normalize(
    const float* __restrict__ Ex, const float* __restrict__ Ey,
    float* __restrict__ out)
{
    __shared__ float ws[8];
    const int row = blockIdx.x;
    const int tid = threadIdx.x;
    const bool head = (tid < 128);          // dims [tid*4, tid*4+4) < 512

    if (tid == 0) { out[row] = 0.0f; g_flag[row] = 0; g_flag2[row] = 0; }

    #pragma unroll 1
    for (int side = 0; side < 2; side++) {
        const float4* src = reinterpret_cast<const float4*>(side ? Ey : Ex)
                            + (size_t)row * 256;
        uint32_t* dst = reinterpret_cast<uint32_t*>(side ? g_Yq : g_Xq)
                        + (size_t)row * 256;

        float4 v = src[tid];
        float ss = blk_sum(v.x * v.x + v.y * v.y + v.z * v.z + v.w * v.w, ws, tid);
        float norm = fmaxf(sqrtf(ss), 1e-8f);
        float sc = 127.0f / norm;

        float f0 = v.x * sc, f1 = v.y * sc, f2 = v.z * sc, f3 = v.w * sc;
        int q0 = max(-127, min(127, __float2int_rn(f0)));
        int q1 = max(-127, min(127, __float2int_rn(f1)));
        int q2 = max(-127, min(127, __float2int_rn(f2)));
        int q3 = max(-127, min(127, __float2int_rn(f3)));
        uint32_t p = (uint32_t)(q0 & 0xFF) | ((uint32_t)(q1 & 0xFF) << 8) |
                     ((uint32_t)(q2 & 0xFF) << 16) | ((uint32_t)(q3 & 0xFF) << 24);
        dst[tid] = p;

        float e0 = (float)q0 - f0, e1 = (float)q1 - f1,
              e2 = (float)q2 - f2, e3 = (float)q3 - f3;
        float e2a = e0 * e0 + e1 * e1 + e2 * e2 + e3 * e3;
        float hss = head ? (v.x * v.x + v.y * v.y + v.z * v.z + v.w * v.w) : 0.0f;
        float e2h = blk_sum(head ? e2a : 0.0f, ws, tid);
        float e2f = blk_sum(e2a, ws, tid);
        float hst = blk_sum(hss, ws, tid);

        if (tid == 0) {
            const int mb = side ? 3 : 0;
            float EH = sqrtf(e2h);                          // ||resid_head|| (q)
            float H  = sqrtf(hst) / norm;                   // ||x_hat_head||
            float T  = sqrtf(fmaxf(ss - hst, 0.0f)) / norm; // ||x_hat_tail||
            atomicMax(&g_max8[mb + 0], __float_as_int(EH));
            atomicMax(&g_max8[mb + 1], __float_as_int(H));
            atomicMax(&g_max8[mb + 2], __float_as_int(T));
            atomicMax(&g_max8[6 + side], __float_as_int(sqrtf(e2f)));
        }
        __syncthreads();
    }
}

// ---------------------------------------------------------------------------
// K2: resident-A IMMA over head 512 dims + screen -> compacted flag list.
// grid (64, 32); each CTA: 2 consecutive tn tiles, streaming B (3 stages).
// ---------------------------------------------------------------------------
__global__ void __launch_bounds__(GT_, 2) rqa_gemm()
{
    extern __shared__ char smem_raw[];
    const uint32_t sb = (smem_u32(smem_raw) + 1023u) & ~1023u;
    const uint32_t a_region = sb;
    const uint32_t b_region = sb + A_BYTES;

    const int tid = threadIdx.x;
    const int wid = tid >> 5;
    const int lid = tid & 31;
    const int warp_m = wid & 3;
    const int warp_n = wid >> 2;
    const int tm = blockIdx.x;
    const int tn0 = blockIdx.y * NSPLIT;

    const float ExH = __int_as_float(g_max8[0]);
    const float Hx  = __int_as_float(g_max8[1]);
    const float Tx  = __int_as_float(g_max8[2]);
    const float EyH = __int_as_float(g_max8[3]);
    const float Hy  = __int_as_float(g_max8[4]);
    const float Ty  = __int_as_float(g_max8[5]);
    const float slack = (ExH * Hy + EyH * Hx) * (1.0f / 127.0f)
                      + (ExH * EyH) * (1.0f / 16129.0f);
    const float cut = 0.9f - Tx * Ty - slack;
    const int thr = (int)floorf(cut * 16129.0f) - 1;

    const uint4* Ag = g_Xq + (size_t)tm * BM_ * 64;   // row stride 64 uint4

    const int cp_row = tid >> 3;
    const int cp_v   = tid & 7;

    #pragma unroll
    for (int c = 0; c < NCHUNK; c++) {
        const uint32_t a_base = a_region + c * B_STAGE;
        #pragma unroll
        for (int i = 0; i < 4; i++) {
            const int row = cp_row + i * 32;
            const uint32_t off = swz((uint32_t)(row * 128 + cp_v * 16));
            cp_async16(a_base + off, Ag + (size_t)row * 64 + c * 8 + cp_v);
        }
    }
    CP_COMMIT();

    auto issue_B = [&](int q) {
        const int tn = tn0 + q / NCHUNK;
        const int c  = q % NCHUNK;
        const uint4* Bg = g_Yq + (size_t)tn * BN_ * 64;
        const uint32_t b_base = b_region + (q % 3) * B_STAGE;
        #pragma unroll
        for (int i = 0; i < 4; i++) {
            const int row = cp_row + i * 32;
            const uint32_t off = swz((uint32_t)(row * 128 + cp_v * 16));
            cp_async16(b_base + off, Bg + (size_t)row * 64 + c * 8 + cp_v);
        }
        CP_COMMIT();
    };

    issue_B(0);
    issue_B(1);

    const int a_row_l = warp_m * 32 + (lid & 15);
    const int a_kb_l  = (lid >> 4) * 16;
    const int b_n_l  = warp_n * 64 + ((lid >> 4) & 1) * 8 + (lid & 7);
    const int b_kb_l = ((lid >> 3) & 1) * 16;

    int32_t acc[2][8][4];

    #pragma unroll 1
    for (int q = 0; q < NQ; q++) {
        const int c = q % NCHUNK;
        CP_WAIT(1);
        __syncthreads();

        if (q + 2 < NQ) issue_B(q + 2);

        if (c == 0) {
            #pragma unroll
            for (int i = 0; i < 2; i++)
                #pragma unroll
                for (int j = 0; j < 8; j++)
                    #pragma unroll
                    for (int k = 0; k < 4; k++) acc[i][j][k] = 0;
        }

        const uint32_t a_base = a_region + c * B_STAGE;
        const uint32_t b_base = b_region + (q % 3) * B_STAGE;

        #pragma unroll
        for (int ks = 0; ks < 4; ks++) {
            uint32_t a[2][4];
            #pragma unroll
            for (int i = 0; i < 2; i++) {
                const uint32_t off =
                    swz((uint32_t)((a_row_l + i * 16) * 128 + ks * 32 + a_kb_l));
                ldmatrix_x4(a[i][0], a[i][1], a[i][2], a[i][3], a_base + off);
            }
            uint32_t b[4][4];
            #pragma unroll
            for (int j2 = 0; j2 < 4; j2++) {
                const uint32_t off =
                    swz((uint32_t)((b_n_l + j2 * 16) * 128 + ks * 32 + b_kb_l));
                ldmatrix_x4(b[j2][0], b[j2][1], b[j2][2], b[j2][3], b_base + off);
            }
            #pragma unroll
            for (int i = 0; i < 2; i++)
                #pragma unroll
                for (int j = 0; j < 8; j++) {
                    const int j2 = j >> 1, h = j & 1;
                    mma_s8(acc[i][j], a[i][0], a[i][1], a[i][2], a[i][3],
                           b[j2][2 * h], b[j2][2 * h + 1]);
                }
        }

        if (c == NCHUNK - 1) {
            #pragma unroll
            for (int i = 0; i < 2; i++) {
                #pragma unroll
                for (int h = 0; h < 2; h++) {
                    int f = 0;
                    #pragma unroll
                    for (int j = 0; j < 8; j++)
                        f |= (acc[i][j][2 * h] > thr) | (acc[i][j][2 * h + 1] > thr);
                    f |= __shfl_xor_sync(0xFFFFFFFFu, f, 1);
                    f |= __shfl_xor_sync(0xFFFFFFFFu, f, 2);
                    if ((lid & 3) == 0 && f) {
                        const int row = tm * BM_ + warp_m * 32 + i * 16 + h * 8 + (lid >> 2);
                        if (atomicExch(&g_flag[row], 1) == 0) {
                            int idx = atomicAdd(&g_nflag, 1);
                            g_list[idx] = row;
                        }
                    }
                }
            }
        }
    }
}

// ---------------------------------------------------------------------------
// K3: full-K int8 rescreen of flagged rows. 256 blocks x 256 threads; block b
// owns Ey rows [b*32, b*32+32); loops the flag list.
// ---------------------------------------------------------------------------
__global__ void __launch_bounds__(256) rqa_rescreen()
{
    const int n = g_nflag;
    if (n == 0) return;

    __shared__ uint32_t xs[256];     // one Xq row (1024 int8)
    const int tid = threadIdx.x;
    const int yrow = blockIdx.x * 32 + (tid >> 3);
    const int seg  = tid & 7;        // 8 threads per y row, 128B each

    const float ExF = __int_as_float(g_max8[6]);
    const float EyF = __int_as_float(g_max8[7]);
    const float slack2 = (ExF + EyF) * (1.0f / 127.0f)
                       + (ExF * EyF) * (1.0f / 16129.0f);
    const int thr2 = (int)floorf((0.9f - slack2) * 16129.0f) - 1;

    const uint32_t* Yrow = reinterpret_cast<const uint32_t*>(g_Yq)
                           + (size_t)yrow * 256 + seg * 32;

    #pragma unroll 1
    for (int f = 0; f < n; f++) {
        const int row = g_list[f];
        xs[tid] = reinterpret_cast<const uint32_t*>(g_Xq)[(size_t)row * 256 + tid];
        __syncthreads();

        int acc = 0;
        #pragma unroll 8
        for (int k = 0; k < 32; k++)
            acc = __dp4a((int)xs[seg * 32 + k], (int)Yrow[k], acc);
        acc += __shfl_down_sync(0xFFFFFFFFu, acc, 4, 8);
        acc += __shfl_down_sync(0xFFFFFFFFu, acc, 2, 8);
        acc += __shfl_down_sync(0xFFFFFFFFu, acc, 1, 8);
        if (seg == 0 && acc > thr2) g_flag2[row] = 1;   // benign race
        __syncthreads();
    }
}

// ---------------------------------------------------------------------------
// K4: exact fp32 check for doubly-flagged rows (statistically never runs).
// ---------------------------------------------------------------------------
__global__ void __launch_bounds__(256) rqa_exact(
    const float* __restrict__ Ex, const float* __restrict__ Ey,
    float* __restrict__ out)
{
    __shared__ float xs[DIMS];
    __shared__ float ws[8];
    const int tid = threadIdx.x;

    #pragma unroll 1
    for (int r = 0; r < 256; r++) {
        const int row = blockIdx.x * 256 + r;
        if (g_flag2[row] == 0) continue;            // uniform per block

        float4 v = reinterpret_cast<const float4*>(Ex)[(size_t)row * 256 + tid];
        float ss = blk_sum(v.x * v.x + v.y * v.y + v.z * v.z + v.w * v.w, ws, tid);
        xs[tid * 4 + 0] = v.x; xs[tid * 4 + 1] = v.y;
        xs[tid * 4 + 2] = v.z; xs[tid * 4 + 3] = v.w;
        __syncthreads();
        const float nx = fmaxf(sqrtf(ss), 1e-8f);

        int any = 0;
        for (int m = tid; m < NROWS; m += 256) {
            const float* y = Ey + (size_t)m * DIMS;
            float dot = 0.0f, ssy = 0.0f;
            #pragma unroll 4
            for (int k = 0; k < DIMS; k++) {
                float yv = y[k];
                dot += xs[k] * yv;
                ssy += yv * yv;
            }
            float ny = fmaxf(sqrtf(ssy), 1e-8f);
            if (dot > 0.9f * nx * ny) any = 1;
        }
        if (any) out[row] = 1.0f;
        __syncthreads();
    }
}

// ---------------------------------------------------------------------------
extern "C" void kernel_launch(void* const* d_in, const int* in_sizes, int n_in,
                              void* d_out, int out_size)
{
    const float* Ex = (const float*)d_in[0];
    const float* Ey = (const float*)d_in[1];
    float* out = (float*)d_out;

    cudaFuncSetAttribute(rqa_gemm, cudaFuncAttributeMaxDynamicSharedMemorySize, SMEM_DYN);

    rqa_init<<<1, 32>>>();
    rqa_normalize<<<NROWS, 256>>>(Ex, Ey, out);
    dim3 grid(NROWS / BM_, NROWS / (BN_ * NSPLIT));
    rqa_gemm<<<grid, GT_, SMEM_DYN>>>();
    rqa_rescreen<<<256, 256>>>();
    rqa_exact<<<32, 256>>>(Ex, Ey, out);
}

// round 13
// speedup vs baseline: 1.0110x; 1.0110x over previous
#include <cuda_runtime.h>
#include <cstdint>

// ============================================================================
// simpleRQA: out[n] = any_m( cos_sim(Ex[n], Ey[m]) > 0.9 )
//
// K0: zero atomicMax cells + flag count.
// K1: normalize+quantize rows to int8 (X and Y sides in PARALLEL, 512 thr);
//     head(512)/tail/resid norms -> atomicMax bounds; zero out[]/flags.
// K2: int8 IMMA GEMM over HEAD 512 dims, A resident (64KB), 4 tn tiles/CTA
//     (grid 1024) -- byte-identical to the proven R9 configuration.
// K3: full-K (1024) int8 dp4a rescreen of flagged rows, parallel over Ey.
// K4: exact fp32 check for doubly-flagged rows (statistically none).
// ============================================================================

#define NROWS   8192
#define DIMS    1024
#define BM_     128
#define BN_     128
#define NCHUNK  4                   // 4 chunks of 128 int8 = 512 head dims
#define NSPLIT  4                   // tn tiles per CTA
#define NQ      (NCHUNK * NSPLIT)   // 16 streamed B chunks per CTA
#define GT_     256                 // 8 warps: 4M x 2N

#define A_BYTES      (NCHUNK * BM_ * 128)     // 64 KB resident A
#define B_STAGE      (BN_ * 128)              // 16 KB per B stage
#define SMEM_DYN     (A_BYTES + 3 * B_STAGE + 1024)

static __device__ uint4 g_Xq[(size_t)NROWS * DIMS / 16];
static __device__ uint4 g_Yq[(size_t)NROWS * DIMS / 16];
static __device__ int   g_flag[NROWS];
static __device__ int   g_flag2[NROWS];
static __device__ int   g_list[NROWS];
static __device__ int   g_nflag;
// [0]=ExH [1]=Hx [2]=Tx [3]=EyH [4]=Hy [5]=Ty [6]=ExF [7]=EyF  (float bits)
static __device__ int   g_max8[8];

// ---------------------------------------------------------------------------
static __device__ __forceinline__ uint32_t smem_u32(const void* p) {
    uint32_t a;
    asm("{ .reg .u64 t; cvta.to.shared.u64 t, %1; cvt.u32.u64 %0, t; }"
        : "=r"(a) : "l"(p));
    return a;
}
static __device__ __forceinline__ void cp_async16(uint32_t dst, const void* src) {
    asm volatile("cp.async.cg.shared.global [%0], [%1], 16;"
                 :: "r"(dst), "l"(src) : "memory");
}
#define CP_COMMIT() asm volatile("cp.async.commit_group;" ::: "memory")
#define CP_WAIT(n)  asm volatile("cp.async.wait_group %0;" :: "n"(n) : "memory")

static __device__ __forceinline__ void ldmatrix_x4(
    uint32_t& r0, uint32_t& r1, uint32_t& r2, uint32_t& r3, uint32_t addr) {
    asm volatile("ldmatrix.sync.aligned.m8n8.x4.shared.b16 {%0,%1,%2,%3}, [%4];"
                 : "=r"(r0), "=r"(r1), "=r"(r2), "=r"(r3) : "r"(addr));
}
static __device__ __forceinline__ void mma_s8(
    int32_t* c, uint32_t a0, uint32_t a1, uint32_t a2, uint32_t a3,
    uint32_t b0, uint32_t b1) {
    asm volatile(
        "mma.sync.aligned.m16n8k32.row.col.s32.s8.s8.s32 "
        "{%0,%1,%2,%3}, {%4,%5,%6,%7}, {%8,%9}, {%0,%1,%2,%3};"
        : "+r"(c[0]), "+r"(c[1]), "+r"(c[2]), "+r"(c[3])
        : "r"(a0), "r"(a1), "r"(a2), "r"(a3), "r"(b0), "r"(b1));
}
static __device__ __forceinline__ uint32_t swz(uint32_t off) {
    return off ^ ((off >> 3) & 0x70);
}
static __device__ __forceinline__ float warp_sum(float v) {
    #pragma unroll
    for (int o = 16; o > 0; o >>= 1) v += __shfl_xor_sync(0xFFFFFFFFu, v, o);
    return v;
}
static __device__ __forceinline__ float blk_sum(float v, float* ws, int tid) {
    v = warp_sum(v);
    if ((tid & 31) == 0) ws[tid >> 5] = v;
    __syncthreads();
    float t = ws[0] + ws[1] + ws[2] + ws[3] + ws[4] + ws[5] + ws[6] + ws[7];
    __syncthreads();
    return t;
}

// ---------------------------------------------------------------------------
__global__ void rqa_init()
{
    if (threadIdx.x < 8) g_max8[threadIdx.x] = 0;
    if (threadIdx.x == 8) g_nflag = 0;
}

// ---------------------------------------------------------------------------
// K1: 512 threads/row; warps 0-7 process Ex[row], warps 8-15 process Ey[row].
// Per-half reductions via 16-slot shared arrays; stats batched in one round.
// ---------------------------------------------------------------------------
__global__ void __launch_bounds__(512) rqa_normalize(
    const float* __restrict__ Ex, const float* __restrict__ Ey,
    float* __restrict__ out)
{
    __shared__ float ws1[16], ws2[16], ws3[16], ws4[16];
    const int row  = blockIdx.x;
    const int tid  = threadIdx.x;
    const int side = tid >> 8;              // 0 = X, 1 = Y
    const int t    = tid & 255;
    const int wid  = tid >> 5;              // 0..15
    const int wb   = side * 8;              // this half's ws window
    const bool head = (t < 128);            // dims [t*4, t*4+4) < 512

    if (tid == 0) { out[row] = 0.0f; g_flag[row] = 0; g_flag2[row] = 0; }

    const float4* src = reinterpret_cast<const float4*>(side ? Ey : Ex)
                        + (size_t)row * 256;
    uint32_t* dst = reinterpret_cast<uint32_t*>(side ? g_Yq : g_Xq)
                    + (size_t)row * 256;

    float4 v = src[t];
    // ---- reduction round 1: sum of squares (per half) ----
    {
        float s = warp_sum(v.x * v.x + v.y * v.y + v.z * v.z + v.w * v.w);
        if ((tid & 31) == 0) ws1[wid] = s;
    }
    __syncthreads();
    float ss = ws1[wb + 0] + ws1[wb + 1] + ws1[wb + 2] + ws1[wb + 3]
             + ws1[wb + 4] + ws1[wb + 5] + ws1[wb + 6] + ws1[wb + 7];

    float norm = fmaxf(sqrtf(ss), 1e-8f);
    float sc = 127.0f / norm;

    float f0 = v.x * sc, f1 = v.y * sc, f2 = v.z * sc, f3 = v.w * sc;
    int q0 = max(-127, min(127, __float2int_rn(f0)));
    int q1 = max(-127, min(127, __float2int_rn(f1)));
    int q2 = max(-127, min(127, __float2int_rn(f2)));
    int q3 = max(-127, min(127, __float2int_rn(f3)));
    uint32_t p = (uint32_t)(q0 & 0xFF) | ((uint32_t)(q1 & 0xFF) << 8) |
                 ((uint32_t)(q2 & 0xFF) << 16) | ((uint32_t)(q3 & 0xFF) << 24);
    dst[t] = p;

    // ---- reduction round 2 (batched): resid-head, resid-full, head-ss ----
    float e0 = (float)q0 - f0, e1 = (float)q1 - f1,
          e2 = (float)q2 - f2, e3 = (float)q3 - f3;
    float e2a = e0 * e0 + e1 * e1 + e2 * e2 + e3 * e3;
    float hss = head ? (v.x * v.x + v.y * v.y + v.z * v.z + v.w * v.w) : 0.0f;
    {
        float a = warp_sum(head ? e2a : 0.0f);
        float b = warp_sum(e2a);
        float c = warp_sum(hss);
        if ((tid & 31) == 0) { ws2[wid] = a; ws3[wid] = b; ws4[wid] = c; }
    }
    __syncthreads();

    if (t == 0) {
        float e2h = 0, e2f = 0, hst = 0;
        #pragma unroll
        for (int i = 0; i < 8; i++) {
            e2h += ws2[wb + i]; e2f += ws3[wb + i]; hst += ws4[wb + i];
        }
        const int mb = side ? 3 : 0;
        float EH = sqrtf(e2h);                          // ||resid_head|| (q)
        float H  = sqrtf(hst) / norm;                   // ||x_hat_head||
        float T  = sqrtf(fmaxf(ss - hst, 0.0f)) / norm; // ||x_hat_tail||
        atomicMax(&g_max8[mb + 0], __float_as_int(EH));
        atomicMax(&g_max8[mb + 1], __float_as_int(H));
        atomicMax(&g_max8[mb + 2], __float_as_int(T));
        atomicMax(&g_max8[6 + side], __float_as_int(sqrtf(e2f)));
    }
}

// ---------------------------------------------------------------------------
// K2: resident-A IMMA over head 512 dims + screen -> compacted flag list.
// grid (64, 16); each CTA: 4 consecutive tn tiles, streaming B (3 stages).
// (Byte-identical logic to the measured-best R9 kernel.)
// ---------------------------------------------------------------------------
__global__ void __launch_bounds__(GT_, 2) rqa_gemm()
{
    extern __shared__ char smem_raw[];
    const uint32_t sb = (smem_u32(smem_raw) + 1023u) & ~1023u;
    const uint32_t a_region = sb;
    const uint32_t b_region = sb + A_BYTES;

    const int tid = threadIdx.x;
    const int wid = tid >> 5;
    const int lid = tid & 31;
    const int warp_m = wid & 3;
    const int warp_n = wid >> 2;
    const int tm = blockIdx.x;
    const int tn0 = blockIdx.y * NSPLIT;

    const float ExH = __int_as_float(g_max8[0]);
    const float Hx  = __int_as_float(g_max8[1]);
    const float Tx  = __int_as_float(g_max8[2]);
    const float EyH = __int_as_float(g_max8[3]);
    const float Hy  = __int_as_float(g_max8[4]);
    const float Ty  = __int_as_float(g_max8[5]);
    const float slack = (ExH * Hy + EyH * Hx) * (1.0f / 127.0f)
                      + (ExH * EyH) * (1.0f / 16129.0f);
    const float cut = 0.9f - Tx * Ty - slack;
    const int thr = (int)floorf(cut * 16129.0f) - 1;

    const uint4* Ag = g_Xq + (size_t)tm * BM_ * 64;   // row stride 64 uint4

    const int cp_row = tid >> 3;
    const int cp_v   = tid & 7;

    #pragma unroll
    for (int c = 0; c < NCHUNK; c++) {
        const uint32_t a_base = a_region + c * B_STAGE;
        #pragma unroll
        for (int i = 0; i < 4; i++) {
            const int row = cp_row + i * 32;
            const uint32_t off = swz((uint32_t)(row * 128 + cp_v * 16));
            cp_async16(a_base + off, Ag + (size_t)row * 64 + c * 8 + cp_v);
        }
    }
    CP_COMMIT();

    auto issue_B = [&](int q) {
        const int tn = tn0 + q / NCHUNK;
        const int c  = q % NCHUNK;
        const uint4* Bg = g_Yq + (size_t)tn * BN_ * 64;
        const uint32_t b_base = b_region + (q % 3) * B_STAGE;
        #pragma unroll
        for (int i = 0; i < 4; i++) {
            const int row = cp_row + i * 32;
            const uint32_t off = swz((uint32_t)(row * 128 + cp_v * 16));
            cp_async16(b_base + off, Bg + (size_t)row * 64 + c * 8 + cp_v);
        }
        CP_COMMIT();
    };

    issue_B(0);
    issue_B(1);

    const int a_row_l = warp_m * 32 + (lid & 15);
    const int a_kb_l  = (lid >> 4) * 16;
    const int b_n_l  = warp_n * 64 + ((lid >> 4) & 1) * 8 + (lid & 7);
    const int b_kb_l = ((lid >> 3) & 1) * 16;

    int32_t acc[2][8][4];

    #pragma unroll 1
    for (int q = 0; q < NQ; q++) {
        const int c = q % NCHUNK;
        CP_WAIT(1);
        __syncthreads();

        if (q + 2 < NQ) issue_B(q + 2);

        if (c == 0) {
            #pragma unroll
            for (int i = 0; i < 2; i++)
                #pragma unroll
                for (int j = 0; j < 8; j++)
                    #pragma unroll
                    for (int k = 0; k < 4; k++) acc[i][j][k] = 0;
        }

        const uint32_t a_base = a_region + c * B_STAGE;
        const uint32_t b_base = b_region + (q % 3) * B_STAGE;

        #pragma unroll
        for (int ks = 0; ks < 4; ks++) {
            uint32_t a[2][4];
            #pragma unroll
            for (int i = 0; i < 2; i++) {
                const uint32_t off =
                    swz((uint32_t)((a_row_l + i * 16) * 128 + ks * 32 + a_kb_l));
                ldmatrix_x4(a[i][0], a[i][1], a[i][2], a[i][3], a_base + off);
            }
            uint32_t b[4][4];
            #pragma unroll
            for (int j2 = 0; j2 < 4; j2++) {
                const uint32_t off =
                    swz((uint32_t)((b_n_l + j2 * 16) * 128 + ks * 32 + b_kb_l));
                ldmatrix_x4(b[j2][0], b[j2][1], b[j2][2], b[j2][3], b_base + off);
            }
            #pragma unroll
            for (int i = 0; i < 2; i++)
                #pragma unroll
                for (int j = 0; j < 8; j++) {
                    const int j2 = j >> 1, h = j & 1;
                    mma_s8(acc[i][j], a[i][0], a[i][1], a[i][2], a[i][3],
                           b[j2][2 * h], b[j2][2 * h + 1]);
                }
        }

        if (c == NCHUNK - 1) {
            #pragma unroll
            for (int i = 0; i < 2; i++) {
                #pragma unroll
                for (int h = 0; h < 2; h++) {
                    int f = 0;
                    #pragma unroll
                    for (int j = 0; j < 8; j++)
                        f |= (acc[i][j][2 * h] > thr) | (acc[i][j][2 * h + 1] > thr);
                    f |= __shfl_xor_sync(0xFFFFFFFFu, f, 1);
                    f |= __shfl_xor_sync(0xFFFFFFFFu, f, 2);
                    if ((lid & 3) == 0 && f) {
                        const int row = tm * BM_ + warp_m * 32 + i * 16 + h * 8 + (lid >> 2);
                        if (atomicExch(&g_flag[row], 1) == 0) {
                            int idx = atomicAdd(&g_nflag, 1);
                            g_list[idx] = row;
                        }
                    }
                }
            }
        }
    }
}

// ---------------------------------------------------------------------------
// K3: full-K int8 rescreen of flagged rows. 256 blocks x 256 threads; block b
// owns Ey rows [b*32, b*32+32); loops the flag list.
// ---------------------------------------------------------------------------
__global__ void __launch_bounds__(256) rqa_rescreen()
{
    const int n = g_nflag;
    if (n == 0) return;

    __shared__ uint32_t xs[256];     // one Xq row (1024 int8)
    const int tid = threadIdx.x;
    const int yrow = blockIdx.x * 32 + (tid >> 3);
    const int seg  = tid & 7;        // 8 threads per y row, 128B each

    const float ExF = __int_as_float(g_max8[6]);
    const float EyF = __int_as_float(g_max8[7]);
    const float slack2 = (ExF + EyF) * (1.0f / 127.0f)
                       + (ExF * EyF) * (1.0f / 16129.0f);
    const int thr2 = (int)floorf((0.9f - slack2) * 16129.0f) - 1;

    const uint32_t* Yrow = reinterpret_cast<const uint32_t*>(g_Yq)
                           + (size_t)yrow * 256 + seg * 32;

    #pragma unroll 1
    for (int f = 0; f < n; f++) {
        const int row = g_list[f];
        xs[tid] = reinterpret_cast<const uint32_t*>(g_Xq)[(size_t)row * 256 + tid];
        __syncthreads();

        int acc = 0;
        #pragma unroll 8
        for (int k = 0; k < 32; k++)
            acc = __dp4a((int)xs[seg * 32 + k], (int)Yrow[k], acc);
        acc += __shfl_down_sync(0xFFFFFFFFu, acc, 4, 8);
        acc += __shfl_down_sync(0xFFFFFFFFu, acc, 2, 8);
        acc += __shfl_down_sync(0xFFFFFFFFu, acc, 1, 8);
        if (seg == 0 && acc > thr2) g_flag2[row] = 1;   // benign race
        __syncthreads();
    }
}

// ---------------------------------------------------------------------------
// K4: exact fp32 check for doubly-flagged rows (statistically never runs).
// ---------------------------------------------------------------------------
__global__ void __launch_bounds__(256) rqa_exact(
    const float* __restrict__ Ex, const float* __restrict__ Ey,
    float* __restrict__ out)
{
    __shared__ float xs[DIMS];
    __shared__ float ws[8];
    const int tid = threadIdx.x;

    #pragma unroll 1
    for (int r = 0; r < 256; r++) {
        const int row = blockIdx.x * 256 + r;
        if (g_flag2[row] == 0) continue;            // uniform per block

        float4 v = reinterpret_cast<const float4*>(Ex)[(size_t)row * 256 + tid];
        float ss = blk_sum(v.x * v.x + v.y * v.y + v.z * v.z + v.w * v.w, ws, tid);
        xs[tid * 4 + 0] = v.x; xs[tid * 4 + 1] = v.y;
        xs[tid * 4 + 2] = v.z; xs[tid * 4 + 3] = v.w;
        __syncthreads();
        const float nx = fmaxf(sqrtf(ss), 1e-8f);

        int any = 0;
        for (int m = tid; m < NROWS; m += 256) {
            const float* y = Ey + (size_t)m * DIMS;
            float dot = 0.0f, ssy = 0.0f;
            #pragma unroll 4
            for (int k = 0; k < DIMS; k++) {
                float yv = y[k];
                dot += xs[k] * yv;
                ssy += yv * yv;
            }
            float ny = fmaxf(sqrtf(ssy), 1e-8f);
            if (dot > 0.9f * nx * ny) any = 1;
        }
        if (any) out[row] = 1.0f;
        __syncthreads();
    }
}

// ---------------------------------------------------------------------------
extern "C" void kernel_launch(void* const* d_in, const int* in_sizes, int n_in,
                              void* d_out, int out_size)
{
    const float* Ex = (const float*)d_in[0];
    const float* Ey = (const float*)d_in[1];
    float* out = (float*)d_out;

    cudaFuncSetAttribute(rqa_gemm, cudaFuncAttributeMaxDynamicSharedMemorySize, SMEM_DYN);

    rqa_init<<<1, 32>>>();
    rqa_normalize<<<NROWS, 512>>>(Ex, Ey, out);
    dim3 grid(NROWS / BM_, NROWS / (BN_ * NSPLIT));
    rqa_gemm<<<grid, GT_, SMEM_DYN>>>();
    rqa_rescreen<<<256, 256>>>();
    rqa_exact<<<32, 256>>>(Ex, Ey, out);
}

// round 14
// speedup vs baseline: 1.2575x; 1.2438x over previous
#include <cuda_runtime.h>
#include <cstdint>

// ============================================================================
// simpleRQA: out[n] = any_m( cos_sim(Ex[n], Ey[m]) > 0.9 )
// Ex, Ey: [8192, 1024] fp32.  out: [8192] fp32 (0.0 / 1.0)
//
// Byte-exact resubmission of the measured-best (123.2us) configuration:
// K0: zero the 6 atomicMax cells.
// K1: normalize+quantize rows to int8; per-row head/tail/residual norms ->
//     atomicMax global bounds; zero out[] and flags.
// K2: int8 IMMA GEMM over HEAD 512 dims; A-tile (64KB) resident in SMEM,
//     each CTA loops 4 tn tiles streaming only B chunks (3-stage cp.async).
//     Conservative (worst-case exact, Cauchy-Schwarz) screen -> g_flag.
// K3: exact fp32 fallback for flagged rows (statistically none).
// ============================================================================

#define NROWS   8192
#define DIMS    1024
#define BM_     128
#define BN_     128
#define NCHUNK  4                   // 4 chunks of 128 int8 = 512 head dims
#define NSPLIT  4                   // tn tiles per CTA
#define NQ      (NCHUNK * NSPLIT)   // 16 streamed B chunks per CTA
#define GT_     256                 // 8 warps: 4M x 2N

#define A_BYTES      (NCHUNK * BM_ * 128)     // 64 KB resident A
#define B_STAGE      (BN_ * 128)              // 16 KB per B stage
#define SMEM_DYN     (A_BYTES + 3 * B_STAGE + 1024)

// Quantized int8 operands (8 MB each; full 1024-dim layout, row stride 1KB).
static __device__ uint4 g_Xq[(size_t)NROWS * DIMS / 16];
static __device__ uint4 g_Yq[(size_t)NROWS * DIMS / 16];
static __device__ int   g_flag[NROWS];
// maxima as positive-float bits for int atomicMax:
// [0]=Ex(resid) [1]=Hx(head) [2]=Tx(tail) [3]=Ey [4]=Hy [5]=Ty
static __device__ int   g_max6[6];

// ---------------------------------------------------------------------------
// helpers
// ---------------------------------------------------------------------------
static __device__ __forceinline__ uint32_t smem_u32(const void* p) {
    uint32_t a;
    asm("{ .reg .u64 t; cvta.to.shared.u64 t, %1; cvt.u32.u64 %0, t; }"
        : "=r"(a) : "l"(p));
    return a;
}

static __device__ __forceinline__ void cp_async16(uint32_t dst, const void* src) {
    asm volatile("cp.async.cg.shared.global [%0], [%1], 16;"
                 :: "r"(dst), "l"(src) : "memory");
}
#define CP_COMMIT() asm volatile("cp.async.commit_group;" ::: "memory")
#define CP_WAIT(n)  asm volatile("cp.async.wait_group %0;" :: "n"(n) : "memory")

static __device__ __forceinline__ void ldmatrix_x4(
    uint32_t& r0, uint32_t& r1, uint32_t& r2, uint32_t& r3, uint32_t addr) {
    asm volatile("ldmatrix.sync.aligned.m8n8.x4.shared.b16 {%0,%1,%2,%3}, [%4];"
                 : "=r"(r0), "=r"(r1), "=r"(r2), "=r"(r3) : "r"(addr));
}

static __device__ __forceinline__ void mma_s8(
    int32_t* c, uint32_t a0, uint32_t a1, uint32_t a2, uint32_t a3,
    uint32_t b0, uint32_t b1) {
    asm volatile(
        "mma.sync.aligned.m16n8k32.row.col.s32.s8.s8.s32 "
        "{%0,%1,%2,%3}, {%4,%5,%6,%7}, {%8,%9}, {%0,%1,%2,%3};"
        : "+r"(c[0]), "+r"(c[1]), "+r"(c[2]), "+r"(c[3])
        : "r"(a0), "r"(a1), "r"(a2), "r"(a3), "r"(b0), "r"(b1));
}

static __device__ __forceinline__ uint32_t swz(uint32_t off) {
    return off ^ ((off >> 3) & 0x70);
}

static __device__ __forceinline__ float blk_sum(float v, float* ws, int tid) {
    #pragma unroll
    for (int o = 16; o > 0; o >>= 1) v += __shfl_xor_sync(0xFFFFFFFFu, v, o);
    if ((tid & 31) == 0) ws[tid >> 5] = v;
    __syncthreads();
    float t = ws[0] + ws[1] + ws[2] + ws[3] + ws[4] + ws[5] + ws[6] + ws[7];
    __syncthreads();
    return t;
}

// ---------------------------------------------------------------------------
// K0: reset maxima.
// ---------------------------------------------------------------------------
__global__ void rqa_init()
{
    if (threadIdx.x < 6) g_max6[threadIdx.x] = 0;
}

// ---------------------------------------------------------------------------
// K1: normalize -> int8 quantize; per-row E (resid), H (head), T (tail) norms.
// One block per row; handles Ex[row] and Ey[row]. Also zeroes out[]/flags.
// ---------------------------------------------------------------------------
__global__ void __launch_bounds__(256) rqa_normalize(
    const float* __restrict__ Ex, const float* __restrict__ Ey,
    float* __restrict__ out)
{
    __shared__ float ws[8];
    const int row = blockIdx.x;
    const int tid = threadIdx.x;
    const bool head = (tid < 128);          // threads 0-127 hold dims 0-511

    if (tid == 0) { out[row] = 0.0f; g_flag[row] = 0; }

    #pragma unroll 1
    for (int side = 0; side < 2; side++) {
        const float4* src = reinterpret_cast<const float4*>(side ? Ey : Ex)
                            + (size_t)row * 256;
        uint32_t* dst = reinterpret_cast<uint32_t*>(side ? g_Yq : g_Xq)
                        + (size_t)row * 256;
        const int mb = side ? 3 : 0;

        float4 v = src[tid];
        float ss = blk_sum(v.x * v.x + v.y * v.y + v.z * v.z + v.w * v.w, ws, tid);
        float norm = fmaxf(sqrtf(ss), 1e-8f);
        float sc = 127.0f / norm;

        float f0 = v.x * sc, f1 = v.y * sc, f2 = v.z * sc, f3 = v.w * sc;
        int q0 = max(-127, min(127, __float2int_rn(f0)));
        int q1 = max(-127, min(127, __float2int_rn(f1)));
        int q2 = max(-127, min(127, __float2int_rn(f2)));
        int q3 = max(-127, min(127, __float2int_rn(f3)));
        uint32_t p = (uint32_t)(q0 & 0xFF) | ((uint32_t)(q1 & 0xFF) << 8) |
                     ((uint32_t)(q2 & 0xFF) << 16) | ((uint32_t)(q3 & 0xFF) << 24);
        dst[tid] = p;

        float e0 = (float)q0 - f0, e1 = (float)q1 - f1,
              e2 = (float)q2 - f2, e3 = (float)q3 - f3;
        float e2s = head ? (e0 * e0 + e1 * e1 + e2 * e2 + e3 * e3) : 0.0f;
        float hss = head ? (v.x * v.x + v.y * v.y + v.z * v.z + v.w * v.w) : 0.0f;
        float e2t = blk_sum(e2s, ws, tid);
        float hst = blk_sum(hss, ws, tid);

        if (tid == 0) {
            float E = sqrtf(e2t);                           // ||resid_head|| (q units)
            float H = sqrtf(hst) / norm;                    // ||x_hat_head||
            float T = sqrtf(fmaxf(ss - hst, 0.0f)) / norm;  // ||x_hat_tail||
            atomicMax(&g_max6[mb + 0], __float_as_int(E));
            atomicMax(&g_max6[mb + 1], __float_as_int(H));
            atomicMax(&g_max6[mb + 2], __float_as_int(T));
        }
        __syncthreads();
    }
}

// ---------------------------------------------------------------------------
// K2: resident-A int8 IMMA GEMM over head 512 dims + conservative screen.
// grid = (64 tm, 16 tn-groups); each CTA does NSPLIT=4 consecutive tn tiles.
// SMEM: A[4 chunks x 16KB] | B stages[3 x 16KB].
// ---------------------------------------------------------------------------
__global__ void __launch_bounds__(GT_, 2) rqa_gemm()
{
    extern __shared__ char smem_raw[];
    const uint32_t sb = (smem_u32(smem_raw) + 1023u) & ~1023u;
    const uint32_t a_region = sb;
    const uint32_t b_region = sb + A_BYTES;

    const int tid = threadIdx.x;
    const int wid = tid >> 5;
    const int lid = tid & 31;
    const int warp_m = wid & 3;
    const int warp_n = wid >> 2;
    const int tm = blockIdx.x;                 // 64 M tiles
    const int tn0 = blockIdx.y * NSPLIT;       // first of 4 tn tiles

    // Conservative integer screen threshold (worst-case exact):
    const float Exm = __int_as_float(g_max6[0]);
    const float Hxm = __int_as_float(g_max6[1]);
    const float Txm = __int_as_float(g_max6[2]);
    const float Eym = __int_as_float(g_max6[3]);
    const float Hym = __int_as_float(g_max6[4]);
    const float Tym = __int_as_float(g_max6[5]);
    const float slack = (Exm * Hym + Eym * Hxm) * (1.0f / 127.0f)
                      + (Exm * Eym) * (1.0f / 16129.0f);
    const float cut = 0.9f - Txm * Tym - slack;
    const int thr = (int)floorf(cut * 16129.0f) - 1;

    const uint4* Ag = g_Xq + (size_t)tm * BM_ * 64;    // row stride 64 uint4 (1KB)

    const int cp_row = tid >> 3;               // 0..31 base row, stepped by 32
    const int cp_v   = tid & 7;                // uint4 index within 128B row

    // ---- prologue: load full A (4 chunks) as one group, then B0, B1 ----
    #pragma unroll
    for (int c = 0; c < NCHUNK; c++) {
        const uint32_t a_base = a_region + c * B_STAGE;
        #pragma unroll
        for (int i = 0; i < 4; i++) {
            const int row = cp_row + i * 32;
            const uint32_t off = swz((uint32_t)(row * 128 + cp_v * 16));
            cp_async16(a_base + off, Ag + (size_t)row * 64 + c * 8 + cp_v);
        }
    }
    CP_COMMIT();

    auto issue_B = [&](int q) {                // q in [0, NQ)
        const int tn = tn0 + (q >> 2);
        const int c  = q & 3;
        const uint4* Bg = g_Yq + (size_t)tn * BN_ * 64;
        const uint32_t b_base = b_region + (q % 3) * B_STAGE;
        #pragma unroll
        for (int i = 0; i < 4; i++) {
            const int row = cp_row + i * 32;
            const uint32_t off = swz((uint32_t)(row * 128 + cp_v * 16));
            cp_async16(b_base + off, Bg + (size_t)row * 64 + c * 8 + cp_v);
        }
        CP_COMMIT();
    };

    issue_B(0);
    issue_B(1);

    const int a_row_l = warp_m * 32 + (lid & 15);
    const int a_kb_l  = (lid >> 4) * 16;
    const int b_n_l  = warp_n * 64 + ((lid >> 4) & 1) * 8 + (lid & 7);
    const int b_kb_l = ((lid >> 3) & 1) * 16;

    int32_t acc[2][8][4];

    #pragma unroll 1
    for (int q = 0; q < NQ; q++) {
        CP_WAIT(1);                 // A + B_q complete; B_{q+1} may be in flight
        __syncthreads();

        if (q + 2 < NQ) issue_B(q + 2);   // stage (q+2)%3 was consumed at q-1

        if ((q & 3) == 0) {
            #pragma unroll
            for (int i = 0; i < 2; i++)
                #pragma unroll
                for (int j = 0; j < 8; j++)
                    #pragma unroll
                    for (int k = 0; k < 4; k++) acc[i][j][k] = 0;
        }

        const uint32_t a_base = a_region + (q & 3) * B_STAGE;
        const uint32_t b_base = b_region + (q % 3) * B_STAGE;

        #pragma unroll
        for (int ks = 0; ks < 4; ks++) {
            uint32_t a[2][4];
            #pragma unroll
            for (int i = 0; i < 2; i++) {
                const uint32_t off =
                    swz((uint32_t)((a_row_l + i * 16) * 128 + ks * 32 + a_kb_l));
                ldmatrix_x4(a[i][0], a[i][1], a[i][2], a[i][3], a_base + off);
            }
            uint32_t b[4][4];
            #pragma unroll
            for (int j2 = 0; j2 < 4; j2++) {
                const uint32_t off =
                    swz((uint32_t)((b_n_l + j2 * 16) * 128 + ks * 32 + b_kb_l));
                ldmatrix_x4(b[j2][0], b[j2][1], b[j2][2], b[j2][3], b_base + off);
            }
            #pragma unroll
            for (int i = 0; i < 2; i++)
                #pragma unroll
                for (int j = 0; j < 8; j++) {
                    const int j2 = j >> 1, h = j & 1;
                    mma_s8(acc[i][j], a[i][0], a[i][1], a[i][2], a[i][3],
                           b[j2][2 * h], b[j2][2 * h + 1]);
                }
        }

        if ((q & 3) == 3) {
            // screen this tn tile: flag rows whose head Q-dot could exceed bound
            #pragma unroll
            for (int i = 0; i < 2; i++) {
                #pragma unroll
                for (int h = 0; h < 2; h++) {
                    int f = 0;
                    #pragma unroll
                    for (int j = 0; j < 8; j++)
                        f |= (acc[i][j][2 * h] > thr) | (acc[i][j][2 * h + 1] > thr);
                    f |= __shfl_xor_sync(0xFFFFFFFFu, f, 1);
                    f |= __shfl_xor_sync(0xFFFFFFFFu, f, 2);
                    if ((lid & 3) == 0 && f) {
                        const int row = tm * BM_ + warp_m * 32 + i * 16 + h * 8 + (lid >> 2);
                        g_flag[row] = 1;   // benign race
                    }
                }
            }
        }
    }
}

// ---------------------------------------------------------------------------
// K3: exact fp32 fallback for flagged rows (normally zero rows).
// 256 blocks; each scans 32 rows, processes flagged ones (uniform branch).
// ---------------------------------------------------------------------------
__global__ void __launch_bounds__(256) rqa_fallback(
    const float* __restrict__ Ex, const float* __restrict__ Ey,
    float* __restrict__ out)
{
    __shared__ float xs[DIMS];
    __shared__ float ws[8];
    const int tid = threadIdx.x;

    #pragma unroll 1
    for (int r = 0; r < 32; r++) {
        const int row = blockIdx.x * 32 + r;
        if (g_flag[row] == 0) continue;          // uniform per block

        float4 v = reinterpret_cast<const float4*>(Ex)[(size_t)row * 256 + tid];
        float ss = blk_sum(v.x * v.x + v.y * v.y + v.z * v.z + v.w * v.w, ws, tid);
        xs[tid * 4 + 0] = v.x; xs[tid * 4 + 1] = v.y;
        xs[tid * 4 + 2] = v.z; xs[tid * 4 + 3] = v.w;
        __syncthreads();
        const float nx = fmaxf(sqrtf(ss), 1e-8f);

        int any = 0;
        for (int m = tid; m < NROWS; m += 256) {
            const float* y = Ey + (size_t)m * DIMS;
            float dot = 0.0f, ssy = 0.0f;
            #pragma unroll 4
            for (int k = 0; k < DIMS; k++) {
                float yv = y[k];
                dot += xs[k] * yv;
                ssy += yv * yv;
            }
            float ny = fmaxf(sqrtf(ssy), 1e-8f);
            if (dot > 0.9f * nx * ny) any = 1;
        }
        if (any) out[row] = 1.0f;
        __syncthreads();                         // xs reuse safety
    }
}

// ---------------------------------------------------------------------------
// Launch
// ---------------------------------------------------------------------------
extern "C" void kernel_launch(void* const* d_in, const int* in_sizes, int n_in,
                              void* d_out, int out_size)
{
    const float* Ex = (const float*)d_in[0];
    const float* Ey = (const float*)d_in[1];
    float* out = (float*)d_out;

    cudaFuncSetAttribute(rqa_gemm, cudaFuncAttributeMaxDynamicSharedMemorySize, SMEM_DYN);

    rqa_init<<<1, 32>>>();
    rqa_normalize<<<NROWS, 256>>>(Ex, Ey, out);
    dim3 grid(NROWS / BM_, NROWS / (BN_ * NSPLIT));
    rqa_gemm<<<grid, GT_, SMEM_DYN>>>();
    rqa_fallback<<<256, 256>>>(Ex, Ey, out);
}